// round 13
// baseline (speedup 1.0000x reference)
#include <cuda_runtime.h>
#include <cuda_bf16.h>
#include <cstdint>
#include <math.h>

#define NN 1024
#define KK 32
#define CC 64
#define NB 148
#define CW 15                   // compute warps per block
#define CL 4                    // copy lanes per block (warp 15, lanes 0..3)
#define CHUNK 4096
#define NCHUNK 65536            // 268435456 / 4096

__device__ float g_a[NN*CC];
__device__ float g_b[NN*CC];
__device__ float g_inter[NN*CC];
__device__ float g_rightlast[KK*KK];
__device__ float g_upd[NN*KK*CC];
__device__ int   g_cnt[NN];
__device__ int   g_gB[KK];
__device__ int   g_chunk;

// ---------------------------------------------------------------------------
// kprep: 16 rows per block (64 threads), weights reused 16x. grid=64.
// ---------------------------------------------------------------------------
__global__ void __launch_bounds__(64)
kprep(const float* __restrict__ local, const float* __restrict__ Wa,
      const float* __restrict__ Wb, const float* __restrict__ Wint,
      const float* __restrict__ bint, const int* __restrict__ neigh,
      const int* __restrict__ mask)
{
    __shared__ float sl[16][128];
    int t = threadIdx.x;
    int i0 = blockIdx.x * 16;
    if (blockIdx.x == 0 && t == 0) g_chunk = 0;   // reset copy-chunk pool
    #pragma unroll
    for (int k = 0; k < 32; k++) {
        int idx = k*64 + t;
        sl[idx >> 7][idx & 127] = local[i0*128 + idx];
    }
    __syncthreads();

    float aA[16], aB[16], aI[16];
    #pragma unroll
    for (int r = 0; r < 16; r++) { aA[r] = 0.f; aB[r] = 0.f; aI[r] = 0.f; }
    #pragma unroll 4
    for (int d = 0; d < 128; d++) {
        float wa = Wa[d*CC + t];
        float wb = Wb[d*CC + t];
        float wi = Wint[d*CC + t];
        #pragma unroll
        for (int r = 0; r < 16; r++) {
            float v = sl[r][d];
            aA[r] = fmaf(v, wa, aA[r]);
            aB[r] = fmaf(v, wb, aB[r]);
            aI[r] = fmaf(v, wi, aI[r]);
        }
    }
    float bi = bint[t];
    #pragma unroll
    for (int r = 0; r < 16; r++) {
        g_a[(i0 + r)*CC + t] = aA[r];
        g_b[(i0 + r)*CC + t] = aB[r];
        g_inter[(i0 + r)*CC + t] = aI[r] + bi;
    }

    if (t < 32) {
        for (int r = 0; r < 16; r++) {
            int n = neigh[(i0 + r)*KK + t];
            unsigned bal = __ballot_sync(0xffffffffu, n == -1);
            if (t == 0) g_cnt[i0 + r] = __popc(bal);
        }
    } else {
        if (blockIdx.x == 63) {
            int k = t - 32;
            int nn = neigh[(NN-1)*KK + k];
            g_gB[k] = (nn != -1) ? (mask[nn] != 0) : 0;
        }
    }
}

// ---------------------------------------------------------------------------
// kright: right-projection of row N-1 edges
// ---------------------------------------------------------------------------
__global__ void kright(const float* __restrict__ pair, const float* __restrict__ pupd,
                       const int* __restrict__ neigh, const float* __restrict__ Waug,
                       const float* __restrict__ Wr, const float* __restrict__ br,
                       const float* __restrict__ lng, const float* __restrict__ lnb)
{
    __shared__ float sWaug[4096];
    __shared__ float sWr[2048];
    __shared__ float spu[32][64];
    __shared__ float slp[32][64];
    int tid = threadIdx.x; // 1024
    for (int idx = tid; idx < 4096; idx += 1024) sWaug[idx] = Waug[idx];
    for (int idx = tid; idx < 2048; idx += 1024) sWr[idx]   = Wr[idx];
    __syncthreads();
    int w = tid >> 5, l = tid & 31;
    int n  = neigh[(NN-1)*KK + w];
    int nb = n < 0 ? n + NN : n;
    float2 x  = ((const float2*)pair)[((size_t)(NN-1)*NN + nb)*32 + l];
    float2 p  = ((const float2*)pupd)[(size_t)((NN-1)*KK + w)*32 + l];
    float2 aa = ((const float2*)g_a)[(NN-1)*32 + l];
    float2 bb = ((const float2*)g_b)[nb*32 + l];
    float pux = p.x + aa.x + bb.x, puy = p.y + aa.y + bb.y;
    float s1 = x.x + x.y, s2 = x.x*x.x + x.y*x.y;
    #pragma unroll
    for (int off = 16; off; off >>= 1) {
        s1 += __shfl_xor_sync(0xffffffffu, s1, off);
        s2 += __shfl_xor_sync(0xffffffffu, s2, off);
    }
    float m = s1 * (1.f/64.f);
    float v = s2 * (1.f/64.f) - m*m;
    float rs = rsqrtf(v + 1e-5f);
    float lpx = (x.x - m)*rs*lng[2*l]   + lnb[2*l];
    float lpy = (x.y - m)*rs*lng[2*l+1] + lnb[2*l+1];
    spu[w][2*l] = pux; spu[w][2*l+1] = puy;
    __syncwarp();
    #pragma unroll 8
    for (int d = 0; d < 64; d++) {
        float pv = spu[w][d];
        float2 wv = ((const float2*)(sWaug + d*64))[l];
        lpx = fmaf(pv, wv.x, lpx);
        lpy = fmaf(pv, wv.y, lpy);
    }
    slp[w][2*l] = lpx; slp[w][2*l+1] = lpy;
    __syncwarp();
    float acc = br[l];
    #pragma unroll 8
    for (int d = 0; d < 64; d++) acc = fmaf(slp[w][d], sWr[d*32 + l], acc);
    g_rightlast[w*32 + l] = acc;
}

__device__ __forceinline__ float gelu_t(float v) {
    float u = 0.7978845608028654f * (v + 0.044715f*v*v*v);
    float t;
    asm("tanh.approx.f32 %0, %1;" : "=f"(t) : "f"(u));
    return 0.5f * v * (1.0f + t);
}

// ---- TMA 1D bulk helpers ----
__device__ __forceinline__ uint32_t smem_u32(const void* p) {
    uint32_t a;
    asm("{ .reg .u64 t; cvta.to.shared.u64 t, %1; cvt.u32.u64 %0, t; }" : "=r"(a) : "l"(p));
    return a;
}
__device__ __forceinline__ void mbar_init(uint32_t mbar) {
    asm volatile("mbarrier.init.shared.b64 [%0], %1;" :: "r"(mbar), "r"(1u) : "memory");
}
__device__ __forceinline__ void mbar_expect(uint32_t mbar, uint32_t bytes) {
    asm volatile("mbarrier.arrive.expect_tx.shared.b64 _, [%0], %1;" :: "r"(mbar), "r"(bytes) : "memory");
}
__device__ __forceinline__ void mbar_wait(uint32_t mbar, uint32_t parity) {
    uint32_t done;
    do {
        asm volatile("{\n\t.reg .pred p;\n\t"
                     "mbarrier.try_wait.parity.shared.b64 p, [%1], %2;\n\t"
                     "selp.b32 %0, 1, 0, p;\n\t}"
                     : "=r"(done) : "r"(mbar), "r"(parity) : "memory");
    } while (!done);
}
__device__ __forceinline__ void bulk_ld(uint32_t dst_smem, const void* src, uint32_t mbar) {
    asm volatile("cp.async.bulk.shared::cluster.global.mbarrier::complete_tx::bytes "
                 "[%0], [%1], %2, [%3];"
                 :: "r"(dst_smem), "l"(src), "r"((uint32_t)CHUNK), "r"(mbar) : "memory");
}
__device__ __forceinline__ void bulk_st(void* dst, uint32_t src_smem) {
    asm volatile("cp.async.bulk.global.shared::cta.bulk_group [%0], [%1], %2;"
                 :: "l"(dst), "r"(src_smem), "r"((uint32_t)CHUNK) : "memory");
    asm volatile("cp.async.bulk.commit_group;" ::: "memory");
}

// Per-lane TMA copy: 3 buffers x 4KB FIFO with reload-lag-1 pipelining.
// Each calling thread has independent bulk-group state and own mbarriers.
__device__ void tma_copy_lane(char* bufbase, const float* __restrict__ pair, float* __restrict__ out)
{
    const char* src = (const char*)pair;
    char* dst = (char*)out;
    uint32_t buf0 = smem_u32(bufbase);
    uint32_t mb0  = buf0 + 3*CHUNK;
    #pragma unroll
    for (int s = 0; s < 3; s++) mbar_init(mb0 + s*8);
    asm volatile("fence.proxy.async.shared::cta;" ::: "memory");

    int chunk[3]; int ph[3] = {0, 0, 0};
    #pragma unroll
    for (int s = 0; s < 3; s++) {
        int c = atomicAdd(&g_chunk, 1);
        chunk[s] = c;
        if (c < NCHUNK) {
            mbar_expect(mb0 + s*8, CHUNK);
            bulk_ld(buf0 + s*CHUNK, src + (size_t)c*CHUNK, mb0 + s*8);
        }
    }
    int k = 0;
    while (true) {
        int s = k - (k/3)*3;
        int c = chunk[s];
        if (c >= NCHUNK) break;
        mbar_wait(mb0 + s*8, (uint32_t)(ph[s] & 1));
        ph[s] ^= 1;
        bulk_st(dst + (size_t)c*CHUNK, buf0 + s*CHUNK);
        if (k >= 1) {
            // all stores older than the newest have drained their smem reads
            asm volatile("cp.async.bulk.wait_group.read 1;" ::: "memory");
            int pk = k - 1;
            int ps = pk - (pk/3)*3;
            int nc = atomicAdd(&g_chunk, 1);
            chunk[ps] = nc;
            if (nc < NCHUNK) {
                mbar_expect(mb0 + ps*8, CHUNK);
                bulk_ld(buf0 + ps*CHUNK, src + (size_t)nc*CHUNK, mb0 + ps*8);
            }
        }
        k++;
    }
    asm volatile("cp.async.bulk.wait_group 0;" ::: "memory");
}

// ---------------------------------------------------------------------------
// kedge: 148 blocks x 512 threads. Warps 0-14 compute edges -> g_upd.
//        Warp 15 lanes 0-3 each run an independent TMA chunk-stealing copy
//        FIFO (out = pair), concurrent with compute on EVERY SM from t=0.
// ---------------------------------------------------------------------------
__global__ void __launch_bounds__(512, 1)
kedge(const float* __restrict__ pair, const float* __restrict__ pupd,
      const int* __restrict__ neigh,
      const float* __restrict__ Waug, const float* __restrict__ Wlin,
      const float* __restrict__ Wleft, const float* __restrict__ bleft,
      const float* __restrict__ W1, const float* __restrict__ W2,
      const float* __restrict__ lng, const float* __restrict__ lnb,
      float* __restrict__ out)
{
    extern __shared__ float sm[];
    float* sWaug  = sm;                 // 4096
    float* sWlin  = sWaug  + 4096;      // 4096
    float* sWleft = sWlin  + 4096;      // 2048
    float* sW1    = sWleft + 2048;      // 4096
    float* sW2    = sW1    + 4096;      // 8192
    float* sRL    = sW2    + 8192;      // 1024
    float* sMisc  = sRL    + 1024;      // 192
    float* scratch = sMisc + 192;       // 15 warps * 1152 = 17280
    char*  tmabuf = (char*)(sm + 41024); // CL * (3*CHUNK + 32)

    int tid = threadIdx.x;
    for (int idx = tid; idx < 4096; idx += 512) sWaug[idx]  = Waug[idx];
    for (int idx = tid; idx < 4096; idx += 512) sWlin[idx]  = Wlin[idx];
    for (int idx = tid; idx < 2048; idx += 512) sWleft[idx] = Wleft[idx];
    for (int idx = tid; idx < 4096; idx += 512) sW1[idx]    = W1[idx];
    for (int idx = tid; idx < 8192; idx += 512) sW2[idx]    = W2[idx];
    for (int idx = tid; idx < 1024; idx += 512) sRL[idx]    = g_rightlast[idx];
    if (tid < 32)               sMisc[tid] = (float)g_gB[tid];
    if (tid >= 32 && tid < 96)  sMisc[tid] = lng[tid - 32];
    if (tid >= 96 && tid < 160) sMisc[tid] = lnb[tid - 96];
    if (tid >= 160 && tid < 192) sMisc[tid] = bleft[tid - 160];
    __syncthreads();

    int warp = tid >> 5, lane = tid & 31;

    if (warp == CW) {
        if (lane < CL)
            tma_copy_lane(tmabuf + lane*(3*CHUNK + 32), pair, out);
        return;
    }

    float* pu4 = scratch + warp*1152;
    float* lp4 = pu4 + 256;
    float* z4  = lp4 + 256;
    float* h4  = z4  + 128;

    float2 lg = ((const float2*)(sMisc + 32))[lane];
    float2 lb = ((const float2*)(sMisc + 96))[lane];
    float  bl = sMisc[160 + lane];

    for (int g = blockIdx.x*CW + warp; g < (NN*KK)/4; g += NB*CW) {
        int e0 = g*4;
        int i  = e0 >> 5;
        int jb = e0 & 31;
        int cnti = g_cnt[i];
        float2 aa  = ((const float2*)g_a)[i*32 + lane];
        float2 itv = ((const float2*)g_inter)[i*32 + lane];

        int nw[4]; float gate[4]; float2 x[4], pu[4];
        #pragma unroll
        for (int e = 0; e < 4; e++) {
            int n = neigh[i*KK + jb + e];
            int w = n < 0 ? n + NN : n;
            nw[e] = w;
            x[e] = ((const float2*)pair)[((size_t)i*NN + w)*32 + lane];
            float2 p  = ((const float2*)pupd)[(size_t)(e0 + e)*32 + lane];
            float2 bb = ((const float2*)g_b)[w*32 + lane];
            pu[e].x = p.x + aa.x + bb.x;
            pu[e].y = p.y + aa.y + bb.y;
            gate[e] = (cnti > 0 && n != -1 && sMisc[jb + e] > 0.5f) ? 1.f : 0.f;
        }

        float s1[4], s2[4];
        #pragma unroll
        for (int e = 0; e < 4; e++) {
            s1[e] = x[e].x + x[e].y;
            s2[e] = x[e].x*x[e].x + x[e].y*x[e].y;
        }
        #pragma unroll
        for (int off = 16; off; off >>= 1)
            #pragma unroll
            for (int e = 0; e < 4; e++) {
                s1[e] += __shfl_xor_sync(0xffffffffu, s1[e], off);
                s2[e] += __shfl_xor_sync(0xffffffffu, s2[e], off);
            }
        float2 lp[4];
        #pragma unroll
        for (int e = 0; e < 4; e++) {
            float m = s1[e]*(1.f/64.f);
            float v = s2[e]*(1.f/64.f) - m*m;
            float rs = rsqrtf(v + 1e-5f);
            lp[e].x = (x[e].x - m)*rs*lg.x + lb.x;
            lp[e].y = (x[e].y - m)*rs*lg.y + lb.y;
        }

        ((float4*)pu4)[lane]      = make_float4(pu[0].x, pu[1].x, pu[2].x, pu[3].x);
        ((float4*)pu4)[32 + lane] = make_float4(pu[0].y, pu[1].y, pu[2].y, pu[3].y);
        __syncwarp();
        #pragma unroll 4
        for (int u = 0; u < 32; u++) {
            float4 p = ((const float4*)pu4)[u];
            float4 q = ((const float4*)pu4)[32 + u];
            float2 w0 = ((const float2*)(sWaug + (2*u)*CC))[lane];
            float2 w1 = ((const float2*)(sWaug + (2*u + 1)*CC))[lane];
            float pe[4] = {p.x, p.y, p.z, p.w};
            float qe[4] = {q.x, q.y, q.z, q.w};
            #pragma unroll
            for (int e = 0; e < 4; e++) {
                lp[e].x = fmaf(pe[e], w0.x, lp[e].x);
                lp[e].y = fmaf(pe[e], w0.y, lp[e].y);
                lp[e].x = fmaf(qe[e], w1.x, lp[e].x);
                lp[e].y = fmaf(qe[e], w1.y, lp[e].y);
            }
        }

        ((float4*)lp4)[lane]      = make_float4(lp[0].x, lp[1].x, lp[2].x, lp[3].x);
        ((float4*)lp4)[32 + lane] = make_float4(lp[0].y, lp[1].y, lp[2].y, lp[3].y);
        __syncwarp();
        float2 lin[4]; float lef[4];
        #pragma unroll
        for (int e = 0; e < 4; e++) { lin[e].x = 0.f; lin[e].y = 0.f; lef[e] = bl; }
        #pragma unroll 4
        for (int u = 0; u < 32; u++) {
            float4 p = ((const float4*)lp4)[u];
            float4 q = ((const float4*)lp4)[32 + u];
            float2 wl0 = ((const float2*)(sWlin + (2*u)*CC))[lane];
            float2 wl1 = ((const float2*)(sWlin + (2*u + 1)*CC))[lane];
            float wf0 = sWleft[(2*u)*32 + lane];
            float wf1 = sWleft[(2*u + 1)*32 + lane];
            float pe[4] = {p.x, p.y, p.z, p.w};
            float qe[4] = {q.x, q.y, q.z, q.w};
            #pragma unroll
            for (int e = 0; e < 4; e++) {
                lin[e].x = fmaf(pe[e], wl0.x, lin[e].x);
                lin[e].y = fmaf(pe[e], wl0.y, lin[e].y);
                lin[e].x = fmaf(qe[e], wl1.x, lin[e].x);
                lin[e].y = fmaf(qe[e], wl1.y, lin[e].y);
                lef[e]   = fmaf(pe[e], wf0, lef[e]);
                lef[e]   = fmaf(qe[e], wf1, lef[e]);
            }
        }

        float4 zz = make_float4(lef[0] + sRL[(jb+0)*32 + lane],
                                lef[1] + sRL[(jb+1)*32 + lane],
                                lef[2] + sRL[(jb+2)*32 + lane],
                                lef[3] + sRL[(jb+3)*32 + lane]);
        ((float4*)z4)[lane] = zz;
        __syncwarp();

        float h[16];
        #pragma unroll
        for (int q = 0; q < 16; q++) h[q] = 0.f;
        #pragma unroll 4
        for (int s = 0; s < 32; s++) {
            float4 zb = ((const float4*)z4)[s];
            float ze[4] = {zb.x, zb.y, zb.z, zb.w};
            #pragma unroll
            for (int q = 0; q < 4; q++) {
                float wv = sW1[s*128 + q*32 + lane];
                #pragma unroll
                for (int e = 0; e < 4; e++) h[q*4 + e] = fmaf(ze[e], wv, h[q*4 + e]);
            }
        }
        #pragma unroll
        for (int q = 0; q < 16; q++) h[q] = gelu_t(h[q]);
        #pragma unroll
        for (int q = 0; q < 4; q++)
            ((float4*)h4)[q*32 + lane] = make_float4(h[q*4+0], h[q*4+1], h[q*4+2], h[q*4+3]);
        __syncwarp();

        float2 o[4];
        #pragma unroll
        for (int e = 0; e < 4; e++) { o[e].x = 0.f; o[e].y = 0.f; }
        #pragma unroll 4
        for (int t = 0; t < 128; t++) {
            float4 hb = ((const float4*)h4)[t];
            float2 wv = ((const float2*)(sW2 + t*CC))[lane];
            float he[4] = {hb.x, hb.y, hb.z, hb.w};
            #pragma unroll
            for (int e = 0; e < 4; e++) {
                o[e].x = fmaf(he[e], wv.x, o[e].x);
                o[e].y = fmaf(he[e], wv.y, o[e].y);
            }
        }

        #pragma unroll
        for (int e = 0; e < 4; e++) {
            float2 r;
            r.x = gate[e]*o[e].x + itv.x + lin[e].x;
            r.y = gate[e]*o[e].y + itv.y + lin[e].y;
            ((float2*)g_upd)[(size_t)(e0 + e)*32 + lane] = r;
        }
        __syncwarp();
    }
}

// ---------------------------------------------------------------------------
// kscatter: out[i, neigh(i,j)] += g_upd[e]
// ---------------------------------------------------------------------------
__global__ void __launch_bounds__(512)
kscatter(const int* __restrict__ neigh, float* __restrict__ out)
{
    int gid = blockIdx.x * 512 + threadIdx.x;
    int e = gid >> 5, lane = gid & 31;
    int i = e >> 5;
    int n = neigh[e];
    int w = n < 0 ? n + NN : n;
    float2 u = ((const float2*)g_upd)[(size_t)e*32 + lane];
    float* dst = out + ((size_t)i*NN + w)*CC + 2*lane;
    atomicAdd(dst,     u.x);
    atomicAdd(dst + 1, u.y);
}

extern "C" void kernel_launch(void* const* d_in, const int* in_sizes, int n_in,
                              void* d_out, int out_size)
{
    const float* local  = (const float*)d_in[0];
    const float* pair   = (const float*)d_in[1];
    const float* pupd   = (const float*)d_in[2];
    const int*   neigh  = (const int*)  d_in[3];
    const int*   mask   = (const int*)  d_in[4];
    const float* Wa     = (const float*)d_in[5];
    const float* Wb     = (const float*)d_in[6];
    const float* lng    = (const float*)d_in[7];
    const float* lnb    = (const float*)d_in[8];
    const float* Waug   = (const float*)d_in[9];
    const float* Wlin   = (const float*)d_in[10];
    const float* Wleft  = (const float*)d_in[11];
    const float* bleft  = (const float*)d_in[12];
    const float* Wright = (const float*)d_in[13];
    const float* bright = (const float*)d_in[14];
    const float* W1     = (const float*)d_in[15];
    const float* W2     = (const float*)d_in[16];
    const float* Wint   = (const float*)d_in[17];
    const float* bint   = (const float*)d_in[18];
    float* out = (float*)d_out;

    kprep<<<64, 64>>>(local, Wa, Wb, Wint, bint, neigh, mask);
    kright<<<1, 1024>>>(pair, pupd, neigh, Waug, Wright, bright, lng, lnb);

    // 41024 floats compute (164096B) + 4 lanes * (3*4KB + 32B mbars)
    const int SMEM = 164096 + CL*(3*CHUNK + 32);   // 213376
    cudaFuncSetAttribute(kedge, cudaFuncAttributeMaxDynamicSharedMemorySize, SMEM);
    kedge<<<NB, 512, SMEM>>>(pair, pupd, neigh, Waug, Wlin, Wleft, bleft,
                             W1, W2, lng, lnb, out);
    kscatter<<<2048, 512>>>(neigh, out);
}

// round 14
// speedup vs baseline: 1.1245x; 1.1245x over previous
#include <cuda_runtime.h>
#include <cuda_bf16.h>
#include <cstdint>
#include <math.h>

#define NN 1024
#define KK 32
#define CC 64
#define NB 148
#define CW 14                   // compute warps per block
#define CHUNK 8192
#define NCHUNK 32768            // 268435456 / 8192
#define FIFO 4

__device__ float g_a[NN*CC];
__device__ float g_b[NN*CC];
__device__ float g_inter[NN*CC];
__device__ float g_rightlast[KK*KK];
__device__ float g_upd[NN*KK*CC];
__device__ int   g_cnt[NN];
__device__ int   g_gB[KK];
__device__ int   g_chunk;

// ---------------------------------------------------------------------------
// kprep: 16 rows per block (64 threads), weights reused 16x. grid=64.
// ---------------------------------------------------------------------------
__global__ void __launch_bounds__(64)
kprep(const float* __restrict__ local, const float* __restrict__ Wa,
      const float* __restrict__ Wb, const float* __restrict__ Wint,
      const float* __restrict__ bint, const int* __restrict__ neigh,
      const int* __restrict__ mask)
{
    __shared__ float sl[16][128];
    int t = threadIdx.x;
    int i0 = blockIdx.x * 16;
    if (blockIdx.x == 0 && t == 0) g_chunk = 0;   // reset copy-chunk pool
    #pragma unroll
    for (int k = 0; k < 32; k++) {
        int idx = k*64 + t;
        sl[idx >> 7][idx & 127] = local[i0*128 + idx];
    }
    __syncthreads();

    float aA[16], aB[16], aI[16];
    #pragma unroll
    for (int r = 0; r < 16; r++) { aA[r] = 0.f; aB[r] = 0.f; aI[r] = 0.f; }
    #pragma unroll 4
    for (int d = 0; d < 128; d++) {
        float wa = Wa[d*CC + t];
        float wb = Wb[d*CC + t];
        float wi = Wint[d*CC + t];
        #pragma unroll
        for (int r = 0; r < 16; r++) {
            float v = sl[r][d];
            aA[r] = fmaf(v, wa, aA[r]);
            aB[r] = fmaf(v, wb, aB[r]);
            aI[r] = fmaf(v, wi, aI[r]);
        }
    }
    float bi = bint[t];
    #pragma unroll
    for (int r = 0; r < 16; r++) {
        g_a[(i0 + r)*CC + t] = aA[r];
        g_b[(i0 + r)*CC + t] = aB[r];
        g_inter[(i0 + r)*CC + t] = aI[r] + bi;
    }

    if (t < 32) {
        for (int r = 0; r < 16; r++) {
            int n = neigh[(i0 + r)*KK + t];
            unsigned bal = __ballot_sync(0xffffffffu, n == -1);
            if (t == 0) g_cnt[i0 + r] = __popc(bal);
        }
    } else {
        if (blockIdx.x == 63) {
            int k = t - 32;
            int nn = neigh[(NN-1)*KK + k];
            g_gB[k] = (nn != -1) ? (mask[nn] != 0) : 0;
        }
    }
}

// ---------------------------------------------------------------------------
// kright: right-projection of row N-1 edges
// ---------------------------------------------------------------------------
__global__ void kright(const float* __restrict__ pair, const float* __restrict__ pupd,
                       const int* __restrict__ neigh, const float* __restrict__ Waug,
                       const float* __restrict__ Wr, const float* __restrict__ br,
                       const float* __restrict__ lng, const float* __restrict__ lnb)
{
    __shared__ float sWaug[4096];
    __shared__ float sWr[2048];
    __shared__ float spu[32][64];
    __shared__ float slp[32][64];
    int tid = threadIdx.x; // 1024
    for (int idx = tid; idx < 4096; idx += 1024) sWaug[idx] = Waug[idx];
    for (int idx = tid; idx < 2048; idx += 1024) sWr[idx]   = Wr[idx];
    __syncthreads();
    int w = tid >> 5, l = tid & 31;
    int n  = neigh[(NN-1)*KK + w];
    int nb = n < 0 ? n + NN : n;
    float2 x  = ((const float2*)pair)[((size_t)(NN-1)*NN + nb)*32 + l];
    float2 p  = ((const float2*)pupd)[(size_t)((NN-1)*KK + w)*32 + l];
    float2 aa = ((const float2*)g_a)[(NN-1)*32 + l];
    float2 bb = ((const float2*)g_b)[nb*32 + l];
    float pux = p.x + aa.x + bb.x, puy = p.y + aa.y + bb.y;
    float s1 = x.x + x.y, s2 = x.x*x.x + x.y*x.y;
    #pragma unroll
    for (int off = 16; off; off >>= 1) {
        s1 += __shfl_xor_sync(0xffffffffu, s1, off);
        s2 += __shfl_xor_sync(0xffffffffu, s2, off);
    }
    float m = s1 * (1.f/64.f);
    float v = s2 * (1.f/64.f) - m*m;
    float rs = rsqrtf(v + 1e-5f);
    float lpx = (x.x - m)*rs*lng[2*l]   + lnb[2*l];
    float lpy = (x.y - m)*rs*lng[2*l+1] + lnb[2*l+1];
    spu[w][2*l] = pux; spu[w][2*l+1] = puy;
    __syncwarp();
    #pragma unroll 8
    for (int d = 0; d < 64; d++) {
        float pv = spu[w][d];
        float2 wv = ((const float2*)(sWaug + d*64))[l];
        lpx = fmaf(pv, wv.x, lpx);
        lpy = fmaf(pv, wv.y, lpy);
    }
    slp[w][2*l] = lpx; slp[w][2*l+1] = lpy;
    __syncwarp();
    float acc = br[l];
    #pragma unroll 8
    for (int d = 0; d < 64; d++) acc = fmaf(slp[w][d], sWr[d*32 + l], acc);
    g_rightlast[w*32 + l] = acc;
}

__device__ __forceinline__ float gelu_t(float v) {
    float u = 0.7978845608028654f * (v + 0.044715f*v*v*v);
    float t;
    asm("tanh.approx.f32 %0, %1;" : "=f"(t) : "f"(u));
    return 0.5f * v * (1.0f + t);
}

// ---- TMA 1D bulk helpers ----
__device__ __forceinline__ uint32_t smem_u32(const void* p) {
    uint32_t a;
    asm("{ .reg .u64 t; cvta.to.shared.u64 t, %1; cvt.u32.u64 %0, t; }" : "=r"(a) : "l"(p));
    return a;
}
__device__ __forceinline__ void mbar_init(uint32_t mbar) {
    asm volatile("mbarrier.init.shared.b64 [%0], %1;" :: "r"(mbar), "r"(1u) : "memory");
}
__device__ __forceinline__ void mbar_expect(uint32_t mbar, uint32_t bytes) {
    asm volatile("mbarrier.arrive.expect_tx.shared.b64 _, [%0], %1;" :: "r"(mbar), "r"(bytes) : "memory");
}
__device__ __forceinline__ void mbar_wait(uint32_t mbar, uint32_t parity) {
    uint32_t done;
    do {
        asm volatile("{\n\t.reg .pred p;\n\t"
                     "mbarrier.try_wait.parity.shared.b64 p, [%1], %2;\n\t"
                     "selp.b32 %0, 1, 0, p;\n\t}"
                     : "=r"(done) : "r"(mbar), "r"(parity) : "memory");
    } while (!done);
}
__device__ __forceinline__ void bulk_ld(uint32_t dst_smem, const void* src, uint32_t mbar) {
    asm volatile("cp.async.bulk.shared::cluster.global.mbarrier::complete_tx::bytes "
                 "[%0], [%1], %2, [%3];"
                 :: "r"(dst_smem), "l"(src), "r"((uint32_t)CHUNK), "r"(mbar) : "memory");
}
__device__ __forceinline__ void bulk_st(void* dst, uint32_t src_smem) {
    asm volatile("cp.async.bulk.global.shared::cta.bulk_group [%0], [%1], %2;"
                 :: "l"(dst), "r"(src_smem), "r"((uint32_t)CHUNK) : "memory");
    asm volatile("cp.async.bulk.commit_group;" ::: "memory");
}

// Per-thread TMA copy: FIFO of 4 x 8KB buffers, lag-1 reload pipelining.
// Caller threads live in DIFFERENT warps (independent issue contexts).
__device__ void tma_copy_lane(char* bufbase, const float* __restrict__ pair, float* __restrict__ out)
{
    const char* src = (const char*)pair;
    char* dst = (char*)out;
    uint32_t buf0 = smem_u32(bufbase);
    uint32_t mb0  = buf0 + FIFO*CHUNK;
    #pragma unroll
    for (int s = 0; s < FIFO; s++) mbar_init(mb0 + s*8);
    asm volatile("fence.proxy.async.shared::cta;" ::: "memory");

    int chunk[FIFO]; int ph[FIFO];
    #pragma unroll
    for (int s = 0; s < FIFO; s++) ph[s] = 0;
    #pragma unroll
    for (int s = 0; s < FIFO; s++) {
        int c = atomicAdd(&g_chunk, 1);
        chunk[s] = c;
        if (c < NCHUNK) {
            mbar_expect(mb0 + s*8, CHUNK);
            bulk_ld(buf0 + s*CHUNK, src + (size_t)c*CHUNK, mb0 + s*8);
        }
    }
    int k = 0;
    while (true) {
        int s = k & (FIFO - 1);
        int c = chunk[s];
        if (c >= NCHUNK) break;
        mbar_wait(mb0 + s*8, (uint32_t)(ph[s] & 1));
        ph[s] ^= 1;
        bulk_st(dst + (size_t)c*CHUNK, buf0 + s*CHUNK);
        if (k >= 1) {
            // all store groups except the newest have finished reading smem
            asm volatile("cp.async.bulk.wait_group.read 1;" ::: "memory");
            int ps = (k - 1) & (FIFO - 1);
            int nc = atomicAdd(&g_chunk, 1);
            chunk[ps] = nc;
            if (nc < NCHUNK) {
                mbar_expect(mb0 + ps*8, CHUNK);
                bulk_ld(buf0 + ps*CHUNK, src + (size_t)nc*CHUNK, mb0 + ps*8);
            }
        }
        k++;
    }
    asm volatile("cp.async.bulk.wait_group 0;" ::: "memory");
}

// ---------------------------------------------------------------------------
// kedge: 148 blocks x 512 threads. Warps 0-13 compute edges -> g_upd
//        (14 warps still only need 4 grid-stride iterations: 2072*4 >= 8192).
//        Lane 0 of warp 14 AND warp 15 each run an independent TMA copy FIFO.
// ---------------------------------------------------------------------------
__global__ void __launch_bounds__(512, 1)
kedge(const float* __restrict__ pair, const float* __restrict__ pupd,
      const int* __restrict__ neigh,
      const float* __restrict__ Waug, const float* __restrict__ Wlin,
      const float* __restrict__ Wleft, const float* __restrict__ bleft,
      const float* __restrict__ W1, const float* __restrict__ W2,
      const float* __restrict__ lng, const float* __restrict__ lnb,
      float* __restrict__ out)
{
    extern __shared__ float sm[];
    float* sWaug  = sm;                 // 4096
    float* sWlin  = sWaug  + 4096;      // 4096
    float* sWleft = sWlin  + 4096;      // 2048
    float* sW1    = sWleft + 2048;      // 4096
    float* sW2    = sW1    + 4096;      // 8192
    float* sRL    = sW2    + 8192;      // 1024
    float* sMisc  = sRL    + 1024;      // 192
    float* scratch = sMisc + 192;       // 14 warps * 1152 = 16128
    char*  tmabuf = (char*)(sm + 39872); // 2 * (FIFO*CHUNK + 64)

    int tid = threadIdx.x;
    for (int idx = tid; idx < 4096; idx += 512) sWaug[idx]  = Waug[idx];
    for (int idx = tid; idx < 4096; idx += 512) sWlin[idx]  = Wlin[idx];
    for (int idx = tid; idx < 2048; idx += 512) sWleft[idx] = Wleft[idx];
    for (int idx = tid; idx < 4096; idx += 512) sW1[idx]    = W1[idx];
    for (int idx = tid; idx < 8192; idx += 512) sW2[idx]    = W2[idx];
    for (int idx = tid; idx < 1024; idx += 512) sRL[idx]    = g_rightlast[idx];
    if (tid < 32)               sMisc[tid] = (float)g_gB[tid];
    if (tid >= 32 && tid < 96)  sMisc[tid] = lng[tid - 32];
    if (tid >= 96 && tid < 160) sMisc[tid] = lnb[tid - 96];
    if (tid >= 160 && tid < 192) sMisc[tid] = bleft[tid - 160];
    __syncthreads();

    int warp = tid >> 5, lane = tid & 31;

    if (warp >= CW) {
        if (lane == 0)
            tma_copy_lane(tmabuf + (warp - CW)*(FIFO*CHUNK + 64), pair, out);
        return;
    }

    float* pu4 = scratch + warp*1152;
    float* lp4 = pu4 + 256;
    float* z4  = lp4 + 256;
    float* h4  = z4  + 128;

    float2 lg = ((const float2*)(sMisc + 32))[lane];
    float2 lb = ((const float2*)(sMisc + 96))[lane];
    float  bl = sMisc[160 + lane];

    for (int g = blockIdx.x*CW + warp; g < (NN*KK)/4; g += NB*CW) {
        int e0 = g*4;
        int i  = e0 >> 5;
        int jb = e0 & 31;
        int cnti = g_cnt[i];
        float2 aa  = ((const float2*)g_a)[i*32 + lane];
        float2 itv = ((const float2*)g_inter)[i*32 + lane];

        int nw[4]; float gate[4]; float2 x[4], pu[4];
        #pragma unroll
        for (int e = 0; e < 4; e++) {
            int n = neigh[i*KK + jb + e];
            int w = n < 0 ? n + NN : n;
            nw[e] = w;
            x[e] = ((const float2*)pair)[((size_t)i*NN + w)*32 + lane];
            float2 p  = ((const float2*)pupd)[(size_t)(e0 + e)*32 + lane];
            float2 bb = ((const float2*)g_b)[w*32 + lane];
            pu[e].x = p.x + aa.x + bb.x;
            pu[e].y = p.y + aa.y + bb.y;
            gate[e] = (cnti > 0 && n != -1 && sMisc[jb + e] > 0.5f) ? 1.f : 0.f;
        }

        float s1[4], s2[4];
        #pragma unroll
        for (int e = 0; e < 4; e++) {
            s1[e] = x[e].x + x[e].y;
            s2[e] = x[e].x*x[e].x + x[e].y*x[e].y;
        }
        #pragma unroll
        for (int off = 16; off; off >>= 1)
            #pragma unroll
            for (int e = 0; e < 4; e++) {
                s1[e] += __shfl_xor_sync(0xffffffffu, s1[e], off);
                s2[e] += __shfl_xor_sync(0xffffffffu, s2[e], off);
            }
        float2 lp[4];
        #pragma unroll
        for (int e = 0; e < 4; e++) {
            float m = s1[e]*(1.f/64.f);
            float v = s2[e]*(1.f/64.f) - m*m;
            float rs = rsqrtf(v + 1e-5f);
            lp[e].x = (x[e].x - m)*rs*lg.x + lb.x;
            lp[e].y = (x[e].y - m)*rs*lg.y + lb.y;
        }

        ((float4*)pu4)[lane]      = make_float4(pu[0].x, pu[1].x, pu[2].x, pu[3].x);
        ((float4*)pu4)[32 + lane] = make_float4(pu[0].y, pu[1].y, pu[2].y, pu[3].y);
        __syncwarp();
        #pragma unroll 4
        for (int u = 0; u < 32; u++) {
            float4 p = ((const float4*)pu4)[u];
            float4 q = ((const float4*)pu4)[32 + u];
            float2 w0 = ((const float2*)(sWaug + (2*u)*CC))[lane];
            float2 w1 = ((const float2*)(sWaug + (2*u + 1)*CC))[lane];
            float pe[4] = {p.x, p.y, p.z, p.w};
            float qe[4] = {q.x, q.y, q.z, q.w};
            #pragma unroll
            for (int e = 0; e < 4; e++) {
                lp[e].x = fmaf(pe[e], w0.x, lp[e].x);
                lp[e].y = fmaf(pe[e], w0.y, lp[e].y);
                lp[e].x = fmaf(qe[e], w1.x, lp[e].x);
                lp[e].y = fmaf(qe[e], w1.y, lp[e].y);
            }
        }

        ((float4*)lp4)[lane]      = make_float4(lp[0].x, lp[1].x, lp[2].x, lp[3].x);
        ((float4*)lp4)[32 + lane] = make_float4(lp[0].y, lp[1].y, lp[2].y, lp[3].y);
        __syncwarp();
        float2 lin[4]; float lef[4];
        #pragma unroll
        for (int e = 0; e < 4; e++) { lin[e].x = 0.f; lin[e].y = 0.f; lef[e] = bl; }
        #pragma unroll 4
        for (int u = 0; u < 32; u++) {
            float4 p = ((const float4*)lp4)[u];
            float4 q = ((const float4*)lp4)[32 + u];
            float2 wl0 = ((const float2*)(sWlin + (2*u)*CC))[lane];
            float2 wl1 = ((const float2*)(sWlin + (2*u + 1)*CC))[lane];
            float wf0 = sWleft[(2*u)*32 + lane];
            float wf1 = sWleft[(2*u + 1)*32 + lane];
            float pe[4] = {p.x, p.y, p.z, p.w};
            float qe[4] = {q.x, q.y, q.z, q.w};
            #pragma unroll
            for (int e = 0; e < 4; e++) {
                lin[e].x = fmaf(pe[e], wl0.x, lin[e].x);
                lin[e].y = fmaf(pe[e], wl0.y, lin[e].y);
                lin[e].x = fmaf(qe[e], wl1.x, lin[e].x);
                lin[e].y = fmaf(qe[e], wl1.y, lin[e].y);
                lef[e]   = fmaf(pe[e], wf0, lef[e]);
                lef[e]   = fmaf(qe[e], wf1, lef[e]);
            }
        }

        float4 zz = make_float4(lef[0] + sRL[(jb+0)*32 + lane],
                                lef[1] + sRL[(jb+1)*32 + lane],
                                lef[2] + sRL[(jb+2)*32 + lane],
                                lef[3] + sRL[(jb+3)*32 + lane]);
        ((float4*)z4)[lane] = zz;
        __syncwarp();

        float h[16];
        #pragma unroll
        for (int q = 0; q < 16; q++) h[q] = 0.f;
        #pragma unroll 4
        for (int s = 0; s < 32; s++) {
            float4 zb = ((const float4*)z4)[s];
            float ze[4] = {zb.x, zb.y, zb.z, zb.w};
            #pragma unroll
            for (int q = 0; q < 4; q++) {
                float wv = sW1[s*128 + q*32 + lane];
                #pragma unroll
                for (int e = 0; e < 4; e++) h[q*4 + e] = fmaf(ze[e], wv, h[q*4 + e]);
            }
        }
        #pragma unroll
        for (int q = 0; q < 16; q++) h[q] = gelu_t(h[q]);
        #pragma unroll
        for (int q = 0; q < 4; q++)
            ((float4*)h4)[q*32 + lane] = make_float4(h[q*4+0], h[q*4+1], h[q*4+2], h[q*4+3]);
        __syncwarp();

        float2 o[4];
        #pragma unroll
        for (int e = 0; e < 4; e++) { o[e].x = 0.f; o[e].y = 0.f; }
        #pragma unroll 4
        for (int t = 0; t < 128; t++) {
            float4 hb = ((const float4*)h4)[t];
            float2 wv = ((const float2*)(sW2 + t*CC))[lane];
            float he[4] = {hb.x, hb.y, hb.z, hb.w};
            #pragma unroll
            for (int e = 0; e < 4; e++) {
                o[e].x = fmaf(he[e], wv.x, o[e].x);
                o[e].y = fmaf(he[e], wv.y, o[e].y);
            }
        }

        #pragma unroll
        for (int e = 0; e < 4; e++) {
            float2 r;
            r.x = gate[e]*o[e].x + itv.x + lin[e].x;
            r.y = gate[e]*o[e].y + itv.y + lin[e].y;
            ((float2*)g_upd)[(size_t)(e0 + e)*32 + lane] = r;
        }
        __syncwarp();
    }
}

// ---------------------------------------------------------------------------
// kscatter: out[i, neigh(i,j)] += g_upd[e]
// ---------------------------------------------------------------------------
__global__ void __launch_bounds__(512)
kscatter(const int* __restrict__ neigh, float* __restrict__ out)
{
    int gid = blockIdx.x * 512 + threadIdx.x;
    int e = gid >> 5, lane = gid & 31;
    int i = e >> 5;
    int n = neigh[e];
    int w = n < 0 ? n + NN : n;
    float2 u = ((const float2*)g_upd)[(size_t)e*32 + lane];
    float* dst = out + ((size_t)i*NN + w)*CC + 2*lane;
    atomicAdd(dst,     u.x);
    atomicAdd(dst + 1, u.y);
}

extern "C" void kernel_launch(void* const* d_in, const int* in_sizes, int n_in,
                              void* d_out, int out_size)
{
    const float* local  = (const float*)d_in[0];
    const float* pair   = (const float*)d_in[1];
    const float* pupd   = (const float*)d_in[2];
    const int*   neigh  = (const int*)  d_in[3];
    const int*   mask   = (const int*)  d_in[4];
    const float* Wa     = (const float*)d_in[5];
    const float* Wb     = (const float*)d_in[6];
    const float* lng    = (const float*)d_in[7];
    const float* lnb    = (const float*)d_in[8];
    const float* Waug   = (const float*)d_in[9];
    const float* Wlin   = (const float*)d_in[10];
    const float* Wleft  = (const float*)d_in[11];
    const float* bleft  = (const float*)d_in[12];
    const float* Wright = (const float*)d_in[13];
    const float* bright = (const float*)d_in[14];
    const float* W1     = (const float*)d_in[15];
    const float* W2     = (const float*)d_in[16];
    const float* Wint   = (const float*)d_in[17];
    const float* bint   = (const float*)d_in[18];
    float* out = (float*)d_out;

    kprep<<<64, 64>>>(local, Wa, Wb, Wint, bint, neigh, mask);
    kright<<<1, 1024>>>(pair, pupd, neigh, Waug, Wright, bright, lng, lnb);

    // 39872 floats compute (159488B) + 2 threads * (4*8KB + 64B mbars)
    const int SMEM = 159488 + 2*(FIFO*CHUNK + 64);   // 225152
    cudaFuncSetAttribute(kedge, cudaFuncAttributeMaxDynamicSharedMemorySize, SMEM);
    kedge<<<NB, 512, SMEM>>>(pair, pupd, neigh, Waug, Wlin, Wleft, bleft,
                             W1, W2, lng, lnb, out);
    kscatter<<<2048, 512>>>(neigh, out);
}